// round 10
// baseline (speedup 1.0000x reference)
#include <cuda_runtime.h>
#include <cuda_bf16.h>
#include <cstdint>

#define NR 4096
#define DD 512
#define TAU_INV 10.0f
#define PK 40                      // padded K stride (80B rows, conflict-free)
#define STAGEB (128 * PK * 2)      // 10240 B: one tile (A or B) per stage
#define STAGEP (2 * STAGEB)        // 20480 B: A+B per stage
#define DYN_SMEM (3 * STAGEP)      // 61440 B: 3 pipeline stages
#define NTILES 528                 // upper triangle of 32x32 tile grid

// ---------------- scratch (static device globals; no allocs) ----------------
__device__ __nv_bfloat16 g_A[NR * DD];   // normalized features, bf16
__device__ float g_denom[NR];
__device__ float g_pos[NR];
__device__ int   g_lab[NR];
__device__ int   g_hist[128];
__device__ float g_loss;
__device__ int   g_done;

// ---------------- PTX helpers ------------------------------------------------
__device__ __forceinline__ uint32_t smem_u32(const void* p) {
    uint32_t a;
    asm("{ .reg .u64 t; cvta.to.shared.u64 t, %1; cvt.u32.u64 %0, t; }"
        : "=r"(a) : "l"(p));
    return a;
}
__device__ __forceinline__ void cp16(uint32_t dst, const void* src) {
    asm volatile("cp.async.cg.shared.global [%0], [%1], 16;\n"
                 :: "r"(dst), "l"(src) : "memory");
}
__device__ __forceinline__ void cp_commit() {
    asm volatile("cp.async.commit_group;\n" ::: "memory");
}
__device__ __forceinline__ void cp_wait0() {
    asm volatile("cp.async.wait_group 0;\n" ::: "memory");
}
__device__ __forceinline__ void cp_wait1() {
    asm volatile("cp.async.wait_group 1;\n" ::: "memory");
}
__device__ __forceinline__ void ldsm4(uint32_t* r, uint32_t addr) {
    asm volatile("ldmatrix.sync.aligned.m8n8.x4.shared.b16 {%0,%1,%2,%3}, [%4];\n"
        : "=r"(r[0]), "=r"(r[1]), "=r"(r[2]), "=r"(r[3]) : "r"(addr) : "memory");
}
__device__ __forceinline__ void mma16816(float* c, const uint32_t* a, const uint32_t* b) {
    asm volatile(
        "mma.sync.aligned.m16n8k16.row.col.f32.bf16.bf16.f32 "
        "{%0,%1,%2,%3}, {%4,%5,%6,%7}, {%8,%9}, {%0,%1,%2,%3};\n"
        : "+f"(c[0]), "+f"(c[1]), "+f"(c[2]), "+f"(c[3])
        : "r"(a[0]), "r"(a[1]), "r"(a[2]), "r"(a[3]), "r"(b[0]), "r"(b[1]));
}

// ---------------- kernel 1: warp-per-row prep + label block ------------------
// blocks 0..511: 8 warps, each normalizes one row (no __syncthreads, MLP=4).
// block 512: label decode + histogram + resets.
__global__ __launch_bounds__(256) void prep_kernel(const float* __restrict__ f,
                                                   const int* __restrict__ p32) {
    int tid = threadIdx.x;

    if (blockIdx.x == 512) {
        __shared__ int hist[128];
        __shared__ int nonzero_odd;
        if (tid == 0) { nonzero_odd = 0; g_loss = 0.f; g_done = 0; }
        if (tid < 128) hist[tid] = 0;
        __syncthreads();
        // int64 little-endian labels in [0,100) -> all odd 32-bit words are 0.
        for (int i = 1 + 2 * tid; i < 2048; i += 512)
            if (p32[i] != 0) nonzero_odd = 1;
        __syncthreads();
        bool is64 = (nonzero_odd == 0);
        for (int i = tid; i < NR; i += 256) {
            int L = is64 ? p32[2 * i] : p32[i];
            g_lab[i] = L;
            atomicAdd(&hist[L & 127], 1);
        }
        __syncthreads();
        if (tid < 128) g_hist[tid] = hist[tid];
        return;
    }

    const int lane = tid & 31, warp = tid >> 5;
    const int row = blockIdx.x * 8 + warp;
    const float4* fr = (const float4*)(f + row * DD);   // 128 float4 per row

    float4 v[4];
    #pragma unroll
    for (int k = 0; k < 4; k++) v[k] = fr[lane + 32 * k];   // 4 independent LDG.128

    float s = 0.f;
    #pragma unroll
    for (int k = 0; k < 4; k++)
        s += v[k].x * v[k].x + v[k].y * v[k].y + v[k].z * v[k].z + v[k].w * v[k].w;
    #pragma unroll
    for (int o = 16; o; o >>= 1) s += __shfl_xor_sync(~0u, s, o);
    float inv = rsqrtf(s);

    uint2* dst = (uint2*)(g_A + row * DD);
    #pragma unroll
    for (int k = 0; k < 4; k++) {
        __nv_bfloat162 h0, h1;
        h0.x = __float2bfloat16(v[k].x * inv); h0.y = __float2bfloat16(v[k].y * inv);
        h1.x = __float2bfloat16(v[k].z * inv); h1.y = __float2bfloat16(v[k].w * inv);
        uint2 u;
        u.x = *reinterpret_cast<uint32_t*>(&h0);
        u.y = *reinterpret_cast<uint32_t*>(&h1);
        dst[lane + 32 * k] = u;
    }
    if (lane == 0) { g_denom[row] = 0.f; g_pos[row] = 0.f; }
}

// ---------------- kernel 2: fused symmetric GEMM + contrastive epilogue -----
// 528 CTAs = upper triangle of 32x32 tiles. Tile 128x128, BK=32, THREE-stage
// cp.async pipeline (dynamic smem), ldmatrix fragments, 8 warps, mma.m16n8k16.
extern __shared__ __nv_bfloat16 dynsmem[];

__global__ __launch_bounds__(256, 2) void gemm_kernel() {
    // linear block index -> triangular (by, bx), bx >= by (integer decode)
    int rem = blockIdx.x;
    int by = 0;
    #pragma unroll 1
    while (rem >= 32 - by) { rem -= 32 - by; by++; }
    int bx = by + rem;
    const bool offDiag = (bx != by);

    __shared__ float sh_pd[4][128];
    __shared__ float sh_pp[4][128];
    __shared__ float sh_cd[2][128];
    __shared__ float sh_cp[2][128];
    __shared__ int labR[128], labC[128];

    const int tid  = threadIdx.x;
    const int lane = tid & 31, warp = tid >> 5;
    const int wm = warp >> 2, wn = warp & 3;       // 2x4 warp grid
    const int g = lane >> 2, t = lane & 3;
    const int rowBase = by * 128;
    const int colBase = bx * 128;

    if (tid < 128) labR[tid] = g_lab[rowBase + tid];
    else           labC[tid - 128] = g_lab[colBase + tid - 128];

    float acc[4][4][4];
    #pragma unroll
    for (int mi = 0; mi < 4; mi++)
        #pragma unroll
        for (int ni = 0; ni < 4; ni++)
            #pragma unroll
            for (int r = 0; r < 4; r++) acc[mi][ni][r] = 0.f;

    // staging: each thread owns chunks (tid*2, tid*2+1); chunk c:
    // row = c>>2, 16B piece w = c&3
    const int cA  = tid * 2;
    const int rA0 = cA >> 2,       wA0 = cA & 3;
    const int rA1 = (cA + 1) >> 2, wA1 = (cA + 1) & 3;

    const uint32_t dyn0 = smem_u32(dynsmem);
    const uint32_t oC0 = (uint32_t)(rA0 * PK + wA0 * 8) * 2;   // A/B share geometry
    const uint32_t oC1 = (uint32_t)(rA1 * PK + wA1 * 8) * 2;
    const __nv_bfloat16* pA0 = &g_A[(rowBase + rA0) * DD + wA0 * 8];
    const __nv_bfloat16* pA1 = &g_A[(rowBase + rA1) * DD + wA1 * 8];
    const __nv_bfloat16* pB0 = &g_A[(colBase + rA0) * DD + wA0 * 8];
    const __nv_bfloat16* pB1 = &g_A[(colBase + rA1) * DD + wA1 * 8];

    // ldmatrix per-thread byte offsets (within a tile)
    const uint32_t offA = (((lane & 15) * PK) + ((lane >> 4) << 3)) * 2;
    const uint32_t offB = ((((lane & 7) + ((lane >> 4) << 3)) * PK) + (((lane >> 3) & 1) << 3)) * 2;
    const uint32_t aOff = offA + (uint32_t)(wm * 64) * PK * 2;            // + stage base
    const uint32_t bOff = offB + (uint32_t)(wn * 32) * PK * 2 + STAGEB;   // B after A

    // prologue: stages 0 and 1 (chunks kt=0,1), one commit group each
    #pragma unroll
    for (int c0 = 0; c0 < 2; c0++) {
        uint32_t base = dyn0 + c0 * STAGEP;
        cp16(base + oC0, pA0 + c0 * 32); cp16(base + oC1, pA1 + c0 * 32);
        cp16(base + STAGEB + oC0, pB0 + c0 * 32); cp16(base + STAGEB + oC1, pB1 + c0 * 32);
        cp_commit();
    }

    int s = 0;   // stage index of current chunk kt
    for (int kt = 0; kt < 16; kt++) {
        if (kt < 15) cp_wait1(); else cp_wait0();   // chunk kt's copies complete
        __syncthreads();                             // also: stage (kt-1)%3 now free
        if (kt + 2 < 16) {
            int s2 = s + 2; if (s2 >= 3) s2 -= 3;   // == (kt-1)%3, freed above
            uint32_t base = dyn0 + s2 * STAGEP;
            int ko = (kt + 2) * 32;
            cp16(base + oC0, pA0 + ko); cp16(base + oC1, pA1 + ko);
            cp16(base + STAGEB + oC0, pB0 + ko); cp16(base + STAGEB + oC1, pB1 + ko);
            cp_commit();
        }
        const uint32_t stBase = dyn0 + s * STAGEP;
        const uint32_t aBase = stBase + aOff;
        const uint32_t bBase = stBase + bOff;
        #pragma unroll
        for (int kk = 0; kk < 32; kk += 16) {
            uint32_t af[4][4], bq[2][4];
            #pragma unroll
            for (int mi = 0; mi < 4; mi++)
                ldsm4(af[mi], aBase + (mi * 16 * PK + kk) * 2);
            #pragma unroll
            for (int p = 0; p < 2; p++)
                ldsm4(bq[p], bBase + (p * 16 * PK + kk) * 2);
            #pragma unroll
            for (int mi = 0; mi < 4; mi++) {
                #pragma unroll
                for (int p = 0; p < 2; p++) {
                    mma16816(acc[mi][2 * p],     af[mi], &bq[p][0]);
                    mma16816(acc[mi][2 * p + 1], af[mi], &bq[p][2]);
                }
            }
        }
        s++; if (s >= 3) s = 0;
    }
    __syncthreads();

    // ---- epilogue: sim = acc/tau; row sums always, column sums if offDiag ----
    float colPD[4][2], colPP[4][2];
    #pragma unroll
    for (int ni = 0; ni < 4; ni++) {
        colPD[ni][0] = colPD[ni][1] = 0.f;
        colPP[ni][0] = colPP[ni][1] = 0.f;
    }

    #pragma unroll
    for (int mi = 0; mi < 4; mi++) {
        #pragma unroll
        for (int h = 0; h < 2; h++) {
            int lr = wm * 64 + mi * 16 + g + 8 * h;   // local row in block
            int gi = rowBase + lr;
            int myLab = labR[lr];
            float pd = 0.f, pp = 0.f;
            #pragma unroll
            for (int ni = 0; ni < 4; ni++) {
                int lc = wn * 32 + ni * 8 + 2 * t;
                float s0 = acc[mi][ni][2 * h]     * TAU_INV;
                float s1 = acc[mi][ni][2 * h + 1] * TAU_INV;
                int gj0 = colBase + lc;
                int cl0 = labC[lc], cl1 = labC[lc + 1];
                float e0 = __expf(s0), e1 = __expf(s1);
                bool m0 = (cl0 == myLab), m1 = (cl1 == myLab);
                if (gj0 != gi)     { pd += e0; if (m0) pp += s0; }
                if (gj0 + 1 != gi) { pd += e1; if (m1) pp += s1; }
                if (offDiag) {
                    colPD[ni][0] += e0; colPD[ni][1] += e1;
                    if (m0) colPP[ni][0] += s0;
                    if (m1) colPP[ni][1] += s1;
                }
            }
            pd += __shfl_xor_sync(~0u, pd, 1); pd += __shfl_xor_sync(~0u, pd, 2);
            pp += __shfl_xor_sync(~0u, pp, 1); pp += __shfl_xor_sync(~0u, pp, 2);
            if (t == 0) { sh_pd[wn][lr] = pd; sh_pp[wn][lr] = pp; }
        }
    }

    // column reduction: over g (lane bits 2,3,4), then over wm via smem
    if (offDiag) {
        #pragma unroll
        for (int ni = 0; ni < 4; ni++) {
            #pragma unroll
            for (int c = 0; c < 2; c++) {
                float vd = colPD[ni][c], vp = colPP[ni][c];
                #pragma unroll
                for (int o = 4; o <= 16; o <<= 1) {
                    vd += __shfl_xor_sync(~0u, vd, o);
                    vp += __shfl_xor_sync(~0u, vp, o);
                }
                if (g == 0) {
                    int lc = wn * 32 + ni * 8 + 2 * t + c;
                    sh_cd[wm][lc] = vd;
                    sh_cp[wm][lc] = vp;
                }
            }
        }
    }
    __syncthreads();
    if (tid < 128) {
        float d = sh_pd[0][tid] + sh_pd[1][tid] + sh_pd[2][tid] + sh_pd[3][tid];
        float p = sh_pp[0][tid] + sh_pp[1][tid] + sh_pp[2][tid] + sh_pp[3][tid];
        atomicAdd(&g_denom[rowBase + tid], d);
        atomicAdd(&g_pos[rowBase + tid], p);
    } else if (offDiag) {
        int j = tid - 128;
        atomicAdd(&g_denom[colBase + j], sh_cd[0][j] + sh_cd[1][j]);
        atomicAdd(&g_pos[colBase + j],   sh_cp[0][j] + sh_cp[1][j]);
    }
}

// ---------------- kernel 3: finalize (32 blocks, last-block writes out) -----
__global__ __launch_bounds__(128) void finalize_kernel(float* __restrict__ out) {
    __shared__ float red[4];
    __shared__ bool isLast;
    int tid = threadIdx.x;
    int i = blockIdx.x * 128 + tid;
    float cnt = (float)(g_hist[g_lab[i] & 127] - 1);
    float s = (g_pos[i] - cnt * __logf(g_denom[i])) / (cnt + 1e-8f);
    #pragma unroll
    for (int o = 16; o; o >>= 1) s += __shfl_xor_sync(~0u, s, o);
    if ((tid & 31) == 0) red[tid >> 5] = s;
    __syncthreads();
    if (tid == 0) {
        float v = red[0] + red[1] + red[2] + red[3];
        atomicAdd(&g_loss, v);
        __threadfence();
        int tck = atomicAdd(&g_done, 1);
        isLast = (tck == 31);
    }
    __syncthreads();
    if (isLast && tid == 0)
        out[0] = -atomicAdd(&g_loss, 0.0f) / (float)NR;
}

// ---------------- launch -----------------------------------------------------
extern "C" void kernel_launch(void* const* d_in, const int* in_sizes, int n_in,
                              void* d_out, int out_size) {
    const float* f   = (const float*)d_in[0];
    const int*   lab = (const int*)d_in[1];   // int32 or int64, autodetected
    float* out = (float*)d_out;

    static int attr_done = 0;
    if (!attr_done) {
        cudaFuncSetAttribute(gemm_kernel,
                             cudaFuncAttributeMaxDynamicSharedMemorySize, DYN_SMEM);
        attr_done = 1;
    }

    prep_kernel<<<513, 256>>>(f, lab);
    gemm_kernel<<<NTILES, 256, DYN_SMEM>>>();
    finalize_kernel<<<32, 128>>>(out);
}

// round 11
// speedup vs baseline: 1.0345x; 1.0345x over previous
#include <cuda_runtime.h>
#include <cuda_bf16.h>
#include <cstdint>

#define NR 4096
#define DD 512
#define TAU_INV 10.0f
#define PK 40                      // padded K stride (80B rows, conflict-free)
#define STAGEB (128 * PK * 2)      // 10240 B: one tile (A or B) per stage
#define STAGEP (2 * STAGEB)        // 20480 B: A+B per stage
#define DYN_SMEM (3 * STAGEP)      // 61440 B: 3 pipeline stages
#define NTILES 528                 // upper triangle of 32x32 tile grid

// ---------------- scratch (static device globals; no allocs) ----------------
__device__ __nv_bfloat16 g_A[NR * DD];   // normalized features, bf16
__device__ float g_denom[NR];
__device__ float g_pos[NR];
__device__ int   g_lab[NR];
__device__ int   g_hist[128];
__device__ float g_loss;
__device__ int   g_done;

// ---------------- PTX helpers ------------------------------------------------
__device__ __forceinline__ uint32_t smem_u32(const void* p) {
    uint32_t a;
    asm("{ .reg .u64 t; cvta.to.shared.u64 t, %1; cvt.u32.u64 %0, t; }"
        : "=r"(a) : "l"(p));
    return a;
}
__device__ __forceinline__ void cp16(uint32_t dst, const void* src) {
    asm volatile("cp.async.cg.shared.global [%0], [%1], 16;\n"
                 :: "r"(dst), "l"(src) : "memory");
}
__device__ __forceinline__ void cp_commit() {
    asm volatile("cp.async.commit_group;\n" ::: "memory");
}
__device__ __forceinline__ void cp_wait0() {
    asm volatile("cp.async.wait_group 0;\n" ::: "memory");
}
__device__ __forceinline__ void cp_wait1() {
    asm volatile("cp.async.wait_group 1;\n" ::: "memory");
}
__device__ __forceinline__ void ldsm4(uint32_t* r, uint32_t addr) {
    asm volatile("ldmatrix.sync.aligned.m8n8.x4.shared.b16 {%0,%1,%2,%3}, [%4];\n"
        : "=r"(r[0]), "=r"(r[1]), "=r"(r[2]), "=r"(r[3]) : "r"(addr) : "memory");
}
__device__ __forceinline__ void mma16816(float* c, const uint32_t* a, const uint32_t* b) {
    asm volatile(
        "mma.sync.aligned.m16n8k16.row.col.f32.bf16.bf16.f32 "
        "{%0,%1,%2,%3}, {%4,%5,%6,%7}, {%8,%9}, {%0,%1,%2,%3};\n"
        : "+f"(c[0]), "+f"(c[1]), "+f"(c[2]), "+f"(c[3])
        : "r"(a[0]), "r"(a[1]), "r"(a[2]), "r"(a[3]), "r"(b[0]), "r"(b[1]));
}

// ---------------- kernel 1: warp-per-row prep + batched label block ----------
// blocks 0..511: 8 warps, each normalizes one row (no __syncthreads, MLP=4).
// block 512: label decode + histogram + resets, with ALL global loads batched
// into registers before any dependent op (kills the serial LDG->atomic chain).
__global__ __launch_bounds__(256) void prep_kernel(const float* __restrict__ f,
                                                   const int* __restrict__ p32) {
    int tid = threadIdx.x;

    if (blockIdx.x == 512) {
        __shared__ int hist[128];
        __shared__ int nonzero_odd;
        if (tid == 0) { nonzero_odd = 0; g_loss = 0.f; g_done = 0; }
        if (tid < 128) hist[tid] = 0;
        // batched int64/int32 detection: odd words of first 2048 (4 loads, MLP=4)
        int dv[4];
        #pragma unroll
        for (int k = 0; k < 4; k++) dv[k] = p32[1 + 2 * tid + 512 * k];
        __syncthreads();
        if (dv[0] | dv[1] | dv[2] | dv[3]) nonzero_odd = 1;
        __syncthreads();
        bool is64 = (nonzero_odd == 0);
        // batched label loads: 16 independent LDGs, THEN stores + hist atomics
        int Lv[16];
        #pragma unroll
        for (int k = 0; k < 16; k++) {
            int i = tid + 256 * k;
            Lv[k] = is64 ? p32[2 * i] : p32[i];
        }
        #pragma unroll
        for (int k = 0; k < 16; k++) {
            int i = tid + 256 * k;
            g_lab[i] = Lv[k];
            atomicAdd(&hist[Lv[k] & 127], 1);
        }
        __syncthreads();
        if (tid < 128) g_hist[tid] = hist[tid];
        return;
    }

    const int lane = tid & 31, warp = tid >> 5;
    const int row = blockIdx.x * 8 + warp;
    const float4* fr = (const float4*)(f + row * DD);   // 128 float4 per row

    float4 v[4];
    #pragma unroll
    for (int k = 0; k < 4; k++) v[k] = fr[lane + 32 * k];   // 4 independent LDG.128

    float s = 0.f;
    #pragma unroll
    for (int k = 0; k < 4; k++)
        s += v[k].x * v[k].x + v[k].y * v[k].y + v[k].z * v[k].z + v[k].w * v[k].w;
    #pragma unroll
    for (int o = 16; o; o >>= 1) s += __shfl_xor_sync(~0u, s, o);
    float inv = rsqrtf(s);

    uint2* dst = (uint2*)(g_A + row * DD);
    #pragma unroll
    for (int k = 0; k < 4; k++) {
        __nv_bfloat162 h0, h1;
        h0.x = __float2bfloat16(v[k].x * inv); h0.y = __float2bfloat16(v[k].y * inv);
        h1.x = __float2bfloat16(v[k].z * inv); h1.y = __float2bfloat16(v[k].w * inv);
        uint2 u;
        u.x = *reinterpret_cast<uint32_t*>(&h0);
        u.y = *reinterpret_cast<uint32_t*>(&h1);
        dst[lane + 32 * k] = u;
    }
    if (lane == 0) { g_denom[row] = 0.f; g_pos[row] = 0.f; }
}

// ---------------- kernel 2: fused symmetric GEMM + contrastive epilogue -----
// 528 CTAs = upper triangle of 32x32 tiles. Tile 128x128, BK=32, THREE-stage
// cp.async pipeline (dynamic smem), ldmatrix fragments, 8 warps, mma.m16n8k16.
extern __shared__ __nv_bfloat16 dynsmem[];

__global__ __launch_bounds__(256, 2) void gemm_kernel() {
    // linear block index -> triangular (by, bx), bx >= by (integer decode)
    int rem = blockIdx.x;
    int by = 0;
    #pragma unroll 1
    while (rem >= 32 - by) { rem -= 32 - by; by++; }
    int bx = by + rem;
    const bool offDiag = (bx != by);

    __shared__ float sh_pd[4][128];
    __shared__ float sh_pp[4][128];
    __shared__ float sh_cd[2][128];
    __shared__ float sh_cp[2][128];
    __shared__ int labR[128], labC[128];

    const int tid  = threadIdx.x;
    const int lane = tid & 31, warp = tid >> 5;
    const int wm = warp >> 2, wn = warp & 3;       // 2x4 warp grid
    const int g = lane >> 2, t = lane & 3;
    const int rowBase = by * 128;
    const int colBase = bx * 128;

    if (tid < 128) labR[tid] = g_lab[rowBase + tid];
    else           labC[tid - 128] = g_lab[colBase + tid - 128];

    float acc[4][4][4];
    #pragma unroll
    for (int mi = 0; mi < 4; mi++)
        #pragma unroll
        for (int ni = 0; ni < 4; ni++)
            #pragma unroll
            for (int r = 0; r < 4; r++) acc[mi][ni][r] = 0.f;

    // staging: each thread owns chunks (tid*2, tid*2+1); chunk c:
    // row = c>>2, 16B piece w = c&3
    const int cA  = tid * 2;
    const int rA0 = cA >> 2,       wA0 = cA & 3;
    const int rA1 = (cA + 1) >> 2, wA1 = (cA + 1) & 3;

    const uint32_t dyn0 = smem_u32(dynsmem);
    const uint32_t oC0 = (uint32_t)(rA0 * PK + wA0 * 8) * 2;   // A/B share geometry
    const uint32_t oC1 = (uint32_t)(rA1 * PK + wA1 * 8) * 2;
    const __nv_bfloat16* pA0 = &g_A[(rowBase + rA0) * DD + wA0 * 8];
    const __nv_bfloat16* pA1 = &g_A[(rowBase + rA1) * DD + wA1 * 8];
    const __nv_bfloat16* pB0 = &g_A[(colBase + rA0) * DD + wA0 * 8];
    const __nv_bfloat16* pB1 = &g_A[(colBase + rA1) * DD + wA1 * 8];

    // ldmatrix per-thread byte offsets (within a tile)
    const uint32_t offA = (((lane & 15) * PK) + ((lane >> 4) << 3)) * 2;
    const uint32_t offB = ((((lane & 7) + ((lane >> 4) << 3)) * PK) + (((lane >> 3) & 1) << 3)) * 2;
    const uint32_t aOff = offA + (uint32_t)(wm * 64) * PK * 2;            // + stage base
    const uint32_t bOff = offB + (uint32_t)(wn * 32) * PK * 2 + STAGEB;   // B after A

    // prologue: stages 0 and 1 (chunks kt=0,1), one commit group each
    #pragma unroll
    for (int c0 = 0; c0 < 2; c0++) {
        uint32_t base = dyn0 + c0 * STAGEP;
        cp16(base + oC0, pA0 + c0 * 32); cp16(base + oC1, pA1 + c0 * 32);
        cp16(base + STAGEB + oC0, pB0 + c0 * 32); cp16(base + STAGEB + oC1, pB1 + c0 * 32);
        cp_commit();
    }

    int s = 0;   // stage index of current chunk kt
    for (int kt = 0; kt < 16; kt++) {
        if (kt < 15) cp_wait1(); else cp_wait0();   // chunk kt's copies complete
        __syncthreads();                             // also: stage (kt-1)%3 now free
        if (kt + 2 < 16) {
            int s2 = s + 2; if (s2 >= 3) s2 -= 3;   // == (kt-1)%3, freed above
            uint32_t base = dyn0 + s2 * STAGEP;
            int ko = (kt + 2) * 32;
            cp16(base + oC0, pA0 + ko); cp16(base + oC1, pA1 + ko);
            cp16(base + STAGEB + oC0, pB0 + ko); cp16(base + STAGEB + oC1, pB1 + ko);
            cp_commit();
        }
        const uint32_t stBase = dyn0 + s * STAGEP;
        const uint32_t aBase = stBase + aOff;
        const uint32_t bBase = stBase + bOff;
        #pragma unroll
        for (int kk = 0; kk < 32; kk += 16) {
            uint32_t af[4][4], bq[2][4];
            #pragma unroll
            for (int mi = 0; mi < 4; mi++)
                ldsm4(af[mi], aBase + (mi * 16 * PK + kk) * 2);
            #pragma unroll
            for (int p = 0; p < 2; p++)
                ldsm4(bq[p], bBase + (p * 16 * PK + kk) * 2);
            #pragma unroll
            for (int mi = 0; mi < 4; mi++) {
                #pragma unroll
                for (int p = 0; p < 2; p++) {
                    mma16816(acc[mi][2 * p],     af[mi], &bq[p][0]);
                    mma16816(acc[mi][2 * p + 1], af[mi], &bq[p][2]);
                }
            }
        }
        s++; if (s >= 3) s = 0;
    }
    __syncthreads();

    // ---- epilogue: sim = acc/tau; row sums always, column sums if offDiag ----
    float colPD[4][2], colPP[4][2];
    #pragma unroll
    for (int ni = 0; ni < 4; ni++) {
        colPD[ni][0] = colPD[ni][1] = 0.f;
        colPP[ni][0] = colPP[ni][1] = 0.f;
    }

    #pragma unroll
    for (int mi = 0; mi < 4; mi++) {
        #pragma unroll
        for (int h = 0; h < 2; h++) {
            int lr = wm * 64 + mi * 16 + g + 8 * h;   // local row in block
            int gi = rowBase + lr;
            int myLab = labR[lr];
            float pd = 0.f, pp = 0.f;
            #pragma unroll
            for (int ni = 0; ni < 4; ni++) {
                int lc = wn * 32 + ni * 8 + 2 * t;
                float s0 = acc[mi][ni][2 * h]     * TAU_INV;
                float s1 = acc[mi][ni][2 * h + 1] * TAU_INV;
                int gj0 = colBase + lc;
                int cl0 = labC[lc], cl1 = labC[lc + 1];
                float e0 = __expf(s0), e1 = __expf(s1);
                bool m0 = (cl0 == myLab), m1 = (cl1 == myLab);
                if (gj0 != gi)     { pd += e0; if (m0) pp += s0; }
                if (gj0 + 1 != gi) { pd += e1; if (m1) pp += s1; }
                if (offDiag) {
                    colPD[ni][0] += e0; colPD[ni][1] += e1;
                    if (m0) colPP[ni][0] += s0;
                    if (m1) colPP[ni][1] += s1;
                }
            }
            pd += __shfl_xor_sync(~0u, pd, 1); pd += __shfl_xor_sync(~0u, pd, 2);
            pp += __shfl_xor_sync(~0u, pp, 1); pp += __shfl_xor_sync(~0u, pp, 2);
            if (t == 0) { sh_pd[wn][lr] = pd; sh_pp[wn][lr] = pp; }
        }
    }

    // column reduction: over g (lane bits 2,3,4), then over wm via smem
    if (offDiag) {
        #pragma unroll
        for (int ni = 0; ni < 4; ni++) {
            #pragma unroll
            for (int c = 0; c < 2; c++) {
                float vd = colPD[ni][c], vp = colPP[ni][c];
                #pragma unroll
                for (int o = 4; o <= 16; o <<= 1) {
                    vd += __shfl_xor_sync(~0u, vd, o);
                    vp += __shfl_xor_sync(~0u, vp, o);
                }
                if (g == 0) {
                    int lc = wn * 32 + ni * 8 + 2 * t + c;
                    sh_cd[wm][lc] = vd;
                    sh_cp[wm][lc] = vp;
                }
            }
        }
    }
    __syncthreads();
    if (tid < 128) {
        float d = sh_pd[0][tid] + sh_pd[1][tid] + sh_pd[2][tid] + sh_pd[3][tid];
        float p = sh_pp[0][tid] + sh_pp[1][tid] + sh_pp[2][tid] + sh_pp[3][tid];
        atomicAdd(&g_denom[rowBase + tid], d);
        atomicAdd(&g_pos[rowBase + tid], p);
    } else if (offDiag) {
        int j = tid - 128;
        atomicAdd(&g_denom[colBase + j], sh_cd[0][j] + sh_cd[1][j]);
        atomicAdd(&g_pos[colBase + j],   sh_cp[0][j] + sh_cp[1][j]);
    }
}

// ---------------- kernel 3: finalize (32 blocks, last-block writes out) -----
__global__ __launch_bounds__(128) void finalize_kernel(float* __restrict__ out) {
    __shared__ float red[4];
    __shared__ bool isLast;
    int tid = threadIdx.x;
    int i = blockIdx.x * 128 + tid;
    float cnt = (float)(g_hist[g_lab[i] & 127] - 1);
    float s = (g_pos[i] - cnt * __logf(g_denom[i])) / (cnt + 1e-8f);
    #pragma unroll
    for (int o = 16; o; o >>= 1) s += __shfl_xor_sync(~0u, s, o);
    if ((tid & 31) == 0) red[tid >> 5] = s;
    __syncthreads();
    if (tid == 0) {
        float v = red[0] + red[1] + red[2] + red[3];
        atomicAdd(&g_loss, v);
        __threadfence();
        int tck = atomicAdd(&g_done, 1);
        isLast = (tck == 31);
    }
    __syncthreads();
    if (isLast && tid == 0)
        out[0] = -atomicAdd(&g_loss, 0.0f) / (float)NR;
}

// ---------------- launch -----------------------------------------------------
extern "C" void kernel_launch(void* const* d_in, const int* in_sizes, int n_in,
                              void* d_out, int out_size) {
    const float* f   = (const float*)d_in[0];
    const int*   lab = (const int*)d_in[1];   // int32 or int64, autodetected
    float* out = (float*)d_out;

    static int attr_done = 0;
    if (!attr_done) {
        cudaFuncSetAttribute(gemm_kernel,
                             cudaFuncAttributeMaxDynamicSharedMemorySize, DYN_SMEM);
        attr_done = 1;
    }

    prep_kernel<<<513, 256>>>(f, lab);
    gemm_kernel<<<NTILES, 256, DYN_SMEM>>>();
    finalize_kernel<<<32, 128>>>(out);
}

// round 12
// speedup vs baseline: 1.0867x; 1.0505x over previous
#include <cuda_runtime.h>
#include <cuda_bf16.h>
#include <cstdint>

#define NR 4096
#define DD 512
#define TAU_INV 10.0f
#define PK 40                      // padded K stride (80B rows, conflict-free)
#define STAGE_A (128 * PK * 2)     // 10240 B: A tile chunk (128 rows x BK)
#define STAGE_B (64 * PK * 2)      // 5120 B:  B tile chunk (64 rows x BK)
#define STAGEP (STAGE_A + STAGE_B) // 15360 B per stage
#define DYN_SMEM (3 * STAGEP)      // 46080 B: 3 pipeline stages
#define NTILES 1056                // tiles (by,bc): 128x64, bc >= 2*by

// ---------------- scratch (static device globals; no allocs) ----------------
__device__ __nv_bfloat16 g_A[NR * DD];   // normalized features, bf16
__device__ float g_denom[NR];
__device__ float g_pos[NR];
__device__ int   g_lab[NR];
__device__ int   g_hist[128];
__device__ float g_loss;
__device__ int   g_done;

// ---------------- PTX helpers ------------------------------------------------
__device__ __forceinline__ uint32_t smem_u32(const void* p) {
    uint32_t a;
    asm("{ .reg .u64 t; cvta.to.shared.u64 t, %1; cvt.u32.u64 %0, t; }"
        : "=r"(a) : "l"(p));
    return a;
}
__device__ __forceinline__ void cp16(uint32_t dst, const void* src) {
    asm volatile("cp.async.cg.shared.global [%0], [%1], 16;\n"
                 :: "r"(dst), "l"(src) : "memory");
}
__device__ __forceinline__ void cp_commit() {
    asm volatile("cp.async.commit_group;\n" ::: "memory");
}
__device__ __forceinline__ void cp_wait0() {
    asm volatile("cp.async.wait_group 0;\n" ::: "memory");
}
__device__ __forceinline__ void cp_wait1() {
    asm volatile("cp.async.wait_group 1;\n" ::: "memory");
}
__device__ __forceinline__ void ldsm4(uint32_t* r, uint32_t addr) {
    asm volatile("ldmatrix.sync.aligned.m8n8.x4.shared.b16 {%0,%1,%2,%3}, [%4];\n"
        : "=r"(r[0]), "=r"(r[1]), "=r"(r[2]), "=r"(r[3]) : "r"(addr) : "memory");
}
__device__ __forceinline__ void mma16816(float* c, const uint32_t* a, const uint32_t* b) {
    asm volatile(
        "mma.sync.aligned.m16n8k16.row.col.f32.bf16.bf16.f32 "
        "{%0,%1,%2,%3}, {%4,%5,%6,%7}, {%8,%9}, {%0,%1,%2,%3};\n"
        : "+f"(c[0]), "+f"(c[1]), "+f"(c[2]), "+f"(c[3])
        : "r"(a[0]), "r"(a[1]), "r"(a[2]), "r"(a[3]), "r"(b[0]), "r"(b[1]));
}

// ---------------- kernel 1: warp-per-row prep + batched label block ----------
__global__ __launch_bounds__(256) void prep_kernel(const float* __restrict__ f,
                                                   const int* __restrict__ p32) {
    int tid = threadIdx.x;

    if (blockIdx.x == 512) {
        __shared__ int hist[128];
        __shared__ int nonzero_odd;
        if (tid == 0) { nonzero_odd = 0; g_loss = 0.f; g_done = 0; }
        if (tid < 128) hist[tid] = 0;
        // batched int64/int32 detection: odd words of first 2048 (MLP=4)
        int dv[4];
        #pragma unroll
        for (int k = 0; k < 4; k++) dv[k] = p32[1 + 2 * tid + 512 * k];
        __syncthreads();
        if (dv[0] | dv[1] | dv[2] | dv[3]) nonzero_odd = 1;
        __syncthreads();
        bool is64 = (nonzero_odd == 0);
        // batched label loads: 16 independent LDGs, THEN stores + hist atomics
        int Lv[16];
        #pragma unroll
        for (int k = 0; k < 16; k++) {
            int i = tid + 256 * k;
            Lv[k] = is64 ? p32[2 * i] : p32[i];
        }
        #pragma unroll
        for (int k = 0; k < 16; k++) {
            int i = tid + 256 * k;
            g_lab[i] = Lv[k];
            atomicAdd(&hist[Lv[k] & 127], 1);
        }
        __syncthreads();
        if (tid < 128) g_hist[tid] = hist[tid];
        return;
    }

    const int lane = tid & 31, warp = tid >> 5;
    const int row = blockIdx.x * 8 + warp;
    const float4* fr = (const float4*)(f + row * DD);

    float4 v[4];
    #pragma unroll
    for (int k = 0; k < 4; k++) v[k] = fr[lane + 32 * k];

    float s = 0.f;
    #pragma unroll
    for (int k = 0; k < 4; k++)
        s += v[k].x * v[k].x + v[k].y * v[k].y + v[k].z * v[k].z + v[k].w * v[k].w;
    #pragma unroll
    for (int o = 16; o; o >>= 1) s += __shfl_xor_sync(~0u, s, o);
    float inv = rsqrtf(s);

    uint2* dst = (uint2*)(g_A + row * DD);
    #pragma unroll
    for (int k = 0; k < 4; k++) {
        __nv_bfloat162 h0, h1;
        h0.x = __float2bfloat16(v[k].x * inv); h0.y = __float2bfloat16(v[k].y * inv);
        h1.x = __float2bfloat16(v[k].z * inv); h1.y = __float2bfloat16(v[k].w * inv);
        uint2 u;
        u.x = *reinterpret_cast<uint32_t*>(&h0);
        u.y = *reinterpret_cast<uint32_t*>(&h1);
        dst[lane + 32 * k] = u;
    }
    if (lane == 0) { g_denom[row] = 0.f; g_pos[row] = 0.f; }
}

// ---------------- kernel 2: symmetric GEMM (128x64 tiles) + epilogue --------
// 1056 CTAs: (by in [0,32), bc in [2*by, 64)) -> rows [by*128,+128), cols
// [bc*64,+64). Tiles partition S; only tiles touching j>i are launched, and a
// uniform j>i predicate counts each unordered pair once (row->i, col->j).
// 8 warps as 4x2 (warp tile 32x32, acc=32 regs), 3-stage cp.async, BK=32,
// 3 CTAs/SM (24 warps/SM vs 16 at the old 128x128 tiling).
extern __shared__ __nv_bfloat16 dynsmem[];

__global__ __launch_bounds__(256, 3) void gemm_kernel() {
    // triangular-ish decode: row by holds 64-2*by tiles
    int rem = blockIdx.x;
    int by = 0;
    #pragma unroll 1
    while (rem >= 64 - 2 * by) { rem -= 64 - 2 * by; by++; }
    int bc = 2 * by + rem;
    const int rowBase = by * 128;
    const int colBase = bc * 64;

    __shared__ float sh_pd[2][128];
    __shared__ float sh_pp[2][128];
    __shared__ float sh_cd[4][64];
    __shared__ float sh_cp[4][64];
    __shared__ int labR[128], labC[64];

    const int tid  = threadIdx.x;
    const int lane = tid & 31, warp = tid >> 5;
    const int wm = warp >> 1, wn = warp & 1;       // 4x2 warp grid
    const int g = lane >> 2, t = lane & 3;

    if (tid < 128) labR[tid] = g_lab[rowBase + tid];
    else if (tid < 192) labC[tid - 128] = g_lab[colBase + tid - 128];

    float acc[2][4][4];
    #pragma unroll
    for (int mi = 0; mi < 2; mi++)
        #pragma unroll
        for (int ni = 0; ni < 4; ni++)
            #pragma unroll
            for (int r = 0; r < 4; r++) acc[mi][ni][r] = 0.f;

    // copy staging. A chunk: 128 rows x 64B = 512 x 16B pieces -> 2/thread.
    // B chunk: 64 rows x 64B = 256 pieces -> 1/thread.
    const int cA  = tid * 2;
    const int rA0 = cA >> 2,       wA0 = cA & 3;
    const int rA1 = (cA + 1) >> 2, wA1 = (cA + 1) & 3;
    const int rB  = tid >> 2,      wB  = tid & 3;

    const uint32_t dyn0 = smem_u32(dynsmem);
    const uint32_t oA0 = (uint32_t)(rA0 * PK + wA0 * 8) * 2;
    const uint32_t oA1 = (uint32_t)(rA1 * PK + wA1 * 8) * 2;
    const uint32_t oB  = (uint32_t)(rB  * PK + wB  * 8) * 2 + STAGE_A;
    const __nv_bfloat16* pA0 = &g_A[(rowBase + rA0) * DD + wA0 * 8];
    const __nv_bfloat16* pA1 = &g_A[(rowBase + rA1) * DD + wA1 * 8];
    const __nv_bfloat16* pB  = &g_A[(colBase + rB)  * DD + wB  * 8];

    // ldmatrix per-thread byte offsets (within a tile)
    const uint32_t offA = (((lane & 15) * PK) + ((lane >> 4) << 3)) * 2;
    const uint32_t offB = ((((lane & 7) + ((lane >> 4) << 3)) * PK) + (((lane >> 3) & 1) << 3)) * 2;
    const uint32_t aOff = offA + (uint32_t)(wm * 32) * PK * 2;
    const uint32_t bOff = offB + (uint32_t)(wn * 32) * PK * 2 + STAGE_A;

    // prologue: stages 0 and 1 (chunks kt=0,1)
    #pragma unroll
    for (int c0 = 0; c0 < 2; c0++) {
        uint32_t base = dyn0 + c0 * STAGEP;
        cp16(base + oA0, pA0 + c0 * 32);
        cp16(base + oA1, pA1 + c0 * 32);
        cp16(base + oB,  pB  + c0 * 32);
        cp_commit();
    }

    int s = 0;   // stage of current chunk kt
    for (int kt = 0; kt < 16; kt++) {
        if (kt < 15) cp_wait1(); else cp_wait0();
        __syncthreads();                         // stage (kt-1)%3 now free
        if (kt + 2 < 16) {
            int s2 = s + 2; if (s2 >= 3) s2 -= 3;
            uint32_t base = dyn0 + s2 * STAGEP;
            int ko = (kt + 2) * 32;
            cp16(base + oA0, pA0 + ko);
            cp16(base + oA1, pA1 + ko);
            cp16(base + oB,  pB  + ko);
            cp_commit();
        }
        const uint32_t stBase = dyn0 + s * STAGEP;
        const uint32_t aBase = stBase + aOff;
        const uint32_t bBase = stBase + bOff;
        #pragma unroll
        for (int kk = 0; kk < 32; kk += 16) {
            uint32_t af[2][4], bq[2][4];
            #pragma unroll
            for (int mi = 0; mi < 2; mi++)
                ldsm4(af[mi], aBase + (mi * 16 * PK + kk) * 2);
            #pragma unroll
            for (int p = 0; p < 2; p++)
                ldsm4(bq[p], bBase + (p * 16 * PK + kk) * 2);
            #pragma unroll
            for (int mi = 0; mi < 2; mi++) {
                #pragma unroll
                for (int p = 0; p < 2; p++) {
                    mma16816(acc[mi][2 * p],     af[mi], &bq[p][0]);
                    mma16816(acc[mi][2 * p + 1], af[mi], &bq[p][2]);
                }
            }
        }
        s++; if (s >= 3) s = 0;
    }
    __syncthreads();

    // ---- epilogue: uniform j>i masking; row sums -> i, col sums -> j --------
    float colPD[4][2], colPP[4][2];
    #pragma unroll
    for (int ni = 0; ni < 4; ni++) {
        colPD[ni][0] = colPD[ni][1] = 0.f;
        colPP[ni][0] = colPP[ni][1] = 0.f;
    }

    #pragma unroll
    for (int mi = 0; mi < 2; mi++) {
        #pragma unroll
        for (int h = 0; h < 2; h++) {
            int lr = wm * 32 + mi * 16 + g + 8 * h;   // local row
            int gi = rowBase + lr;
            int myLab = labR[lr];
            float pd = 0.f, pp = 0.f;
            #pragma unroll
            for (int ni = 0; ni < 4; ni++) {
                int lc = wn * 32 + ni * 8 + 2 * t;
                float s0 = acc[mi][ni][2 * h]     * TAU_INV;
                float s1 = acc[mi][ni][2 * h + 1] * TAU_INV;
                int gj0 = colBase + lc;
                bool u0 = (gj0 > gi), u1 = (gj0 + 1 > gi);   // strict upper only
                float e0 = u0 ? __expf(s0) : 0.f;
                float e1 = u1 ? __expf(s1) : 0.f;
                float p0 = (u0 && labC[lc]     == myLab) ? s0 : 0.f;
                float p1 = (u1 && labC[lc + 1] == myLab) ? s1 : 0.f;
                pd += e0 + e1;
                pp += p0 + p1;
                colPD[ni][0] += e0; colPD[ni][1] += e1;
                colPP[ni][0] += p0; colPP[ni][1] += p1;
            }
            pd += __shfl_xor_sync(~0u, pd, 1); pd += __shfl_xor_sync(~0u, pd, 2);
            pp += __shfl_xor_sync(~0u, pp, 1); pp += __shfl_xor_sync(~0u, pp, 2);
            if (t == 0) { sh_pd[wn][lr] = pd; sh_pp[wn][lr] = pp; }
        }
    }

    // column reduction: over g (lane bits 2,3,4); then over wm via smem
    #pragma unroll
    for (int ni = 0; ni < 4; ni++) {
        #pragma unroll
        for (int c = 0; c < 2; c++) {
            float vd = colPD[ni][c], vp = colPP[ni][c];
            #pragma unroll
            for (int o = 4; o <= 16; o <<= 1) {
                vd += __shfl_xor_sync(~0u, vd, o);
                vp += __shfl_xor_sync(~0u, vp, o);
            }
            if (g == 0) {
                int lc = wn * 32 + ni * 8 + 2 * t + c;
                if (wn == 0) { sh_cd[wm][lc] = vd; sh_cp[wm][lc] = vp; }
                else         { sh_cd[wm][lc] = vd; sh_cp[wm][lc] = vp; }
            }
        }
    }
    __syncthreads();
    if (tid < 128) {
        float d = sh_pd[0][tid] + sh_pd[1][tid];
        float p = sh_pp[0][tid] + sh_pp[1][tid];
        if (d != 0.f || p != 0.f) {
            atomicAdd(&g_denom[rowBase + tid], d);
            atomicAdd(&g_pos[rowBase + tid], p);
        }
    } else if (tid < 192) {
        int j = tid - 128;
        float d = sh_cd[0][j] + sh_cd[1][j] + sh_cd[2][j] + sh_cd[3][j];
        float p = sh_cp[0][j] + sh_cp[1][j] + sh_cp[2][j] + sh_cp[3][j];
        if (d != 0.f || p != 0.f) {
            atomicAdd(&g_denom[colBase + j], d);
            atomicAdd(&g_pos[colBase + j], p);
        }
    }
}

// ---------------- kernel 3: finalize (32 blocks, last-block writes out) -----
__global__ __launch_bounds__(128) void finalize_kernel(float* __restrict__ out) {
    __shared__ float red[4];
    __shared__ bool isLast;
    int tid = threadIdx.x;
    int i = blockIdx.x * 128 + tid;
    float cnt = (float)(g_hist[g_lab[i] & 127] - 1);
    float s = (g_pos[i] - cnt * __logf(g_denom[i])) / (cnt + 1e-8f);
    #pragma unroll
    for (int o = 16; o; o >>= 1) s += __shfl_xor_sync(~0u, s, o);
    if ((tid & 31) == 0) red[tid >> 5] = s;
    __syncthreads();
    if (tid == 0) {
        float v = red[0] + red[1] + red[2] + red[3];
        atomicAdd(&g_loss, v);
        __threadfence();
        int tck = atomicAdd(&g_done, 1);
        isLast = (tck == 31);
    }
    __syncthreads();
    if (isLast && tid == 0)
        out[0] = -atomicAdd(&g_loss, 0.0f) / (float)NR;
}

// ---------------- launch -----------------------------------------------------
extern "C" void kernel_launch(void* const* d_in, const int* in_sizes, int n_in,
                              void* d_out, int out_size) {
    const float* f   = (const float*)d_in[0];
    const int*   lab = (const int*)d_in[1];   // int32 or int64, autodetected
    float* out = (float*)d_out;

    static int attr_done = 0;
    if (!attr_done) {
        cudaFuncSetAttribute(gemm_kernel,
                             cudaFuncAttributeMaxDynamicSharedMemorySize, DYN_SMEM);
        attr_done = 1;
    }

    prep_kernel<<<513, 256>>>(f, lab);
    gemm_kernel<<<NTILES, 256, DYN_SMEM>>>();
    finalize_kernel<<<32, 128>>>(out);
}